// round 2
// baseline (speedup 1.0000x reference)
#include <cuda_runtime.h>
#include <cuda_bf16.h>

#define NN 400000
#define NE 2500000
#define NG 512
#define HD 32
#define INF 7
#define C2 2
#define EPSF 1e-5f
#define NSCAN ((NN + 1023) / 1024)   // 391

// ---------------- device scratch (static, no runtime alloc) ----------------
__device__ float  g_t[NN * HD];      // transformed features (input to aggregation)
__device__ float  g_agg[NN * HD];    // aggregated output
__device__ float  g_deg[NN];
__device__ float  g_dinv[NN];
__device__ int    g_hist[NN];
__device__ int    g_colptr[NN];
__device__ int    g_cursor[NN];
__device__ int    g_esrc[NE];
__device__ float  g_enorm[NE];
__device__ double g_sum[HD];
__device__ double g_sumsq[HD];
__device__ float  g_scale[HD];
__device__ float  g_shift[HD];
__device__ int    g_blocksums[512];
__device__ float  g_pool[NG * HD];
__device__ int    g_goff[NG + 1];

// ---------------- preprocessing ----------------
__global__ void k_init() {
    int i = blockIdx.x * blockDim.x + threadIdx.x;
    if (i < NN) { g_deg[i] = 1.0f; g_hist[i] = 0; }   // deg starts at 1 (self-loop w=1)
    if (i < HD) { g_sum[i] = 0.0; g_sumsq[i] = 0.0; }
}

__global__ void k_edge(const int* __restrict__ ei, const float* __restrict__ ea) {
    int e = blockIdx.x * blockDim.x + threadIdx.x;
    if (e >= NE) return;
    int c = ei[NE + e];
    atomicAdd(&g_deg[c], ea[e]);
    atomicAdd(&g_hist[c], 1);
}

__global__ void k_dinv() {
    int i = blockIdx.x * blockDim.x + threadIdx.x;
    if (i >= NN) return;
    float d = g_deg[i];
    g_dinv[i] = (d > 0.0f) ? rsqrtf(fmaxf(d, EPSF)) : 0.0f;
}

__global__ void k_scan1() {
    __shared__ int s[1024];
    int t = threadIdx.x;
    int i = blockIdx.x * 1024 + t;
    int v = (i < NN) ? g_hist[i] : 0;
    s[t] = v;
    __syncthreads();
    for (int off = 1; off < 1024; off <<= 1) {
        int x = 0;
        if (t >= off) x = s[t - off];
        __syncthreads();
        s[t] += x;
        __syncthreads();
    }
    if (i < NN) g_colptr[i] = s[t] - v;   // exclusive within block
    if (t == 1023) g_blocksums[blockIdx.x] = s[t];
}

__global__ void k_scan2() {
    __shared__ int s[512];
    int t = threadIdx.x;
    int v = (t < NSCAN) ? g_blocksums[t] : 0;
    s[t] = v;
    __syncthreads();
    for (int off = 1; off < 512; off <<= 1) {
        int x = 0;
        if (t >= off) x = s[t - off];
        __syncthreads();
        s[t] += x;
        __syncthreads();
    }
    if (t < NSCAN) g_blocksums[t] = s[t] - v;   // exclusive block offsets
}

__global__ void k_scan3() {
    int i = blockIdx.x * blockDim.x + threadIdx.x;
    if (i >= NN) return;
    int v = g_colptr[i] + g_blocksums[i >> 10];
    g_colptr[i] = v;
    g_cursor[i] = v;
}

__global__ void k_scatter(const int* __restrict__ ei, const float* __restrict__ ea) {
    int e = blockIdx.x * blockDim.x + threadIdx.x;
    if (e >= NE) return;
    int r = ei[e];
    int c = ei[NE + e];
    float w = ea[e];
    int pos = atomicAdd(&g_cursor[c], 1);
    g_esrc[pos] = r;
    g_enorm[pos] = g_dinv[r] * w * g_dinv[c];
}

__global__ void k_goff(const int* __restrict__ batch) {
    int i = blockIdx.x * blockDim.x + threadIdx.x;
    if (i >= NN) return;
    int b = batch[i];
    int prev = (i == 0) ? -1 : batch[i - 1];
    for (int g = prev + 1; g <= b; g++) g_goff[g] = i;
    if (i == NN - 1)
        for (int g = b + 1; g <= NG; g++) g_goff[g] = NN;
}

// ---------------- layer 0 transform: t = x @ W0 ----------------
__global__ void k_t0(const float* __restrict__ x, const float* __restrict__ W0) {
    __shared__ float sW[INF * HD];
    for (int i = threadIdx.x; i < INF * HD; i += blockDim.x) sW[i] = W0[i];
    __syncthreads();
    int n = blockIdx.x * blockDim.x + threadIdx.x;
    if (n >= NN) return;
    float xi[INF];
#pragma unroll
    for (int k = 0; k < INF; k++) xi[k] = x[n * INF + k];
#pragma unroll
    for (int jq = 0; jq < HD / 4; jq++) {
        float4 a = make_float4(0.f, 0.f, 0.f, 0.f);
#pragma unroll
        for (int k = 0; k < INF; k++) {
            float4 w = *(const float4*)&sW[k * HD + jq * 4];
            a.x += xi[k] * w.x; a.y += xi[k] * w.y;
            a.z += xi[k] * w.z; a.w += xi[k] * w.w;
        }
        *(float4*)&g_t[n * HD + jq * 4] = a;
    }
}

// ---------------- aggregation: warp-per-dest, lane-per-feature ----------------
__global__ void k_agg(const float* __restrict__ bias, int doStats) {
    __shared__ double ssum[HD], ssq[HD];
    if (doStats) {
        if (threadIdx.x < HD) { ssum[threadIdx.x] = 0.0; ssq[threadIdx.x] = 0.0; }
        __syncthreads();
    }
    int lane = threadIdx.x & 31;
    int gw = (blockIdx.x * blockDim.x + threadIdx.x) >> 5;
    int nw = (gridDim.x * blockDim.x) >> 5;
    double ls = 0.0, lq = 0.0;
    for (int n = gw; n < NN; n += nw) {
        int st = g_colptr[n];
        int cnt = g_hist[n];
        float di = g_dinv[n];
        float acc = di * di * __ldg(&g_t[n * HD + lane]);
        for (int k = 0; k < cnt; k++) {
            int s = __ldg(&g_esrc[st + k]);
            float nm = __ldg(&g_enorm[st + k]);
            acc += nm * __ldg(&g_t[s * HD + lane]);
        }
        if (bias) acc += bias[lane];
        g_agg[n * HD + lane] = acc;
        if (doStats) { ls += acc; lq += (double)acc * (double)acc; }
    }
    if (doStats) {
        atomicAdd(&ssum[lane], ls);
        atomicAdd(&ssq[lane], lq);
        __syncthreads();
        if (threadIdx.x < HD) {
            atomicAdd(&g_sum[threadIdx.x], ssum[threadIdx.x]);
            atomicAdd(&g_sumsq[threadIdx.x], ssq[threadIdx.x]);
        }
    }
}

// ---------------- finalize BN stats -> per-feature affine ----------------
__global__ void k_fin(const float* __restrict__ gvec, const float* __restrict__ bvec) {
    int j = threadIdx.x;
    if (j < HD) {
        double mean = g_sum[j] / (double)NN;
        double var = g_sumsq[j] / (double)NN - mean * mean;
        float rstd = (float)rsqrt(var + (double)EPSF);
        float sc = gvec[j] * rstd;
        g_scale[j] = sc;
        g_shift[j] = bvec[j] - (float)mean * sc;
        g_sum[j] = 0.0;
        g_sumsq[j] = 0.0;
    }
}

// ---------------- fused bn + relu + transform: t = relu(bn(agg)) @ W ----------------
__global__ void k_bnt(const float* __restrict__ W) {
    __shared__ float sW[HD * HD];
    __shared__ float ssc[HD], ssh[HD];
    for (int i = threadIdx.x; i < HD * HD; i += blockDim.x) sW[i] = W[i];
    if (threadIdx.x < HD) { ssc[threadIdx.x] = g_scale[threadIdx.x]; ssh[threadIdx.x] = g_shift[threadIdx.x]; }
    __syncthreads();
    int n = blockIdx.x * blockDim.x + threadIdx.x;
    if (n >= NN) return;
    float y[HD];
#pragma unroll
    for (int kq = 0; kq < HD / 4; kq++) {
        float4 a = *(const float4*)&g_agg[n * HD + kq * 4];
        y[kq * 4 + 0] = fmaxf(a.x * ssc[kq * 4 + 0] + ssh[kq * 4 + 0], 0.f);
        y[kq * 4 + 1] = fmaxf(a.y * ssc[kq * 4 + 1] + ssh[kq * 4 + 1], 0.f);
        y[kq * 4 + 2] = fmaxf(a.z * ssc[kq * 4 + 2] + ssh[kq * 4 + 2], 0.f);
        y[kq * 4 + 3] = fmaxf(a.w * ssc[kq * 4 + 3] + ssh[kq * 4 + 3], 0.f);
    }
#pragma unroll
    for (int jq = 0; jq < HD / 4; jq++) {
        float4 a = make_float4(0.f, 0.f, 0.f, 0.f);
#pragma unroll
        for (int k = 0; k < HD; k++) {
            float4 w = *(const float4*)&sW[k * HD + jq * 4];
            a.x += y[k] * w.x; a.y += y[k] * w.y;
            a.z += y[k] * w.z; a.w += y[k] * w.w;
        }
        *(float4*)&g_t[n * HD + jq * 4] = a;
    }
}

// ---------------- pool: block per graph (batch is sorted) ----------------
__global__ void k_pool() {
    int g = blockIdx.x;
    int s = g_goff[g], e = g_goff[g + 1];
    int j = threadIdx.x & 31, r = threadIdx.x >> 5;
    float a = 0.f;
    for (int n = s + r; n < e; n += 8) a += g_agg[n * HD + j];
    __shared__ float sm[256];
    sm[threadIdx.x] = a;
    __syncthreads();
    if (threadIdx.x < 32) {
        float p = 0.f;
#pragma unroll
        for (int q = 0; q < 8; q++) p += sm[q * 32 + threadIdx.x];
        g_pool[g * HD + threadIdx.x] = p;
    }
}

// ---------------- final MLP, single block, 512 threads (one per graph) ----------------
__global__ void k_mlp(const float* __restrict__ Wm0, const float* __restrict__ gm,
                      const float* __restrict__ bm, const float* __restrict__ Wm1,
                      const float* __restrict__ bm1, float* __restrict__ out) {
    __shared__ float sW0[HD * HD];
    __shared__ float sW1[HD * C2];
    __shared__ double ssum[HD], ssq[HD];
    __shared__ float ssc[HD], ssh[HD];
    int t = threadIdx.x;
    for (int i = t; i < HD * HD; i += blockDim.x) sW0[i] = Wm0[i];
    if (t < HD * C2) sW1[t] = Wm1[t];
    if (t < HD) { ssum[t] = 0.0; ssq[t] = 0.0; }
    __syncthreads();

    float p[HD];
#pragma unroll
    for (int k = 0; k < HD; k++) p[k] = g_pool[t * HD + k];
    float u[HD];
#pragma unroll
    for (int j = 0; j < HD; j++) {
        float a = 0.f;
#pragma unroll
        for (int k = 0; k < HD; k++) a += p[k] * sW0[k * HD + j];
        u[j] = a;
    }
    // per-feature column sums across 512 rows: warp shuffle then smem double atomics
    int lane = t & 31;
#pragma unroll
    for (int j = 0; j < HD; j++) {
        float v = u[j];
        float q = u[j] * u[j];
        for (int off = 16; off > 0; off >>= 1) {
            v += __shfl_down_sync(0xFFFFFFFFu, v, off);
            q += __shfl_down_sync(0xFFFFFFFFu, q, off);
        }
        if (lane == 0) {
            atomicAdd(&ssum[j], (double)v);
            atomicAdd(&ssq[j], (double)q);
        }
    }
    __syncthreads();
    if (t < HD) {
        double mean = ssum[t] / (double)NG;
        double var = ssq[t] / (double)NG - mean * mean;
        float rstd = (float)rsqrt(var + (double)EPSF);
        ssc[t] = gm[t] * rstd;
        ssh[t] = bm[t] - (float)mean * gm[t] * rstd;
    }
    __syncthreads();
    float o0 = bm1[0], o1 = bm1[1];
#pragma unroll
    for (int k = 0; k < HD; k++) {
        float yv = fmaxf(u[k] * ssc[k] + ssh[k], 0.f);
        o0 += yv * sW1[k * 2 + 0];
        o1 += yv * sW1[k * 2 + 1];
    }
    out[t * 2 + 0] = o0;
    out[t * 2 + 1] = o1;
}

// ---------------- launch ----------------
extern "C" void kernel_launch(void* const* d_in, const int* in_sizes, int n_in,
                              void* d_out, int out_size) {
    const float* x     = (const float*)d_in[0];
    const int*   ei    = (const int*)d_in[1];     // int32: JAX x64 disabled
    const float* ea    = (const float*)d_in[2];
    const int*   batch = (const int*)d_in[3];     // int32
    const float* W0    = (const float*)d_in[4];
    // b0 (d_in[5]) cancels in batchnorm
    const float* W1    = (const float*)d_in[6];
    // b1 cancels
    const float* W2    = (const float*)d_in[8];
    // b2 cancels
    const float* W3    = (const float*)d_in[10];
    const float* b3    = (const float*)d_in[11];
    const float* bn_g  = (const float*)d_in[12];   // [3,32]
    const float* bn_b  = (const float*)d_in[13];
    const float* Wm0   = (const float*)d_in[14];
    // bm0 (d_in[15]) cancels in batchnorm
    const float* bnm_g = (const float*)d_in[16];
    const float* bnm_b = (const float*)d_in[17];
    const float* Wm1   = (const float*)d_in[18];
    const float* bm1   = (const float*)d_in[19];
    float* out = (float*)d_out;

    const int nb = (NN + 255) / 256;
    const int eb = (NE + 255) / 256;

    // per-replay preprocessing: degrees, CSC, graph offsets
    k_init<<<nb, 256>>>();
    k_edge<<<eb, 256>>>(ei, ea);
    k_dinv<<<nb, 256>>>();
    k_scan1<<<NSCAN, 1024>>>();
    k_scan2<<<1, 512>>>();
    k_scan3<<<nb, 256>>>();
    k_scatter<<<eb, 256>>>(ei, ea);
    k_goff<<<nb, 256>>>(batch);

    // layer 0
    k_t0<<<nb, 256>>>(x, W0);
    k_agg<<<2048, 256>>>(nullptr, 1);
    k_fin<<<1, 32>>>(bn_g + 0 * HD, bn_b + 0 * HD);
    k_bnt<<<nb, 256>>>(W1);
    // layer 1
    k_agg<<<2048, 256>>>(nullptr, 1);
    k_fin<<<1, 32>>>(bn_g + 1 * HD, bn_b + 1 * HD);
    k_bnt<<<nb, 256>>>(W2);
    // layer 2
    k_agg<<<2048, 256>>>(nullptr, 1);
    k_fin<<<1, 32>>>(bn_g + 2 * HD, bn_b + 2 * HD);
    k_bnt<<<nb, 256>>>(W3);
    // layer 3 (bias, no bn)
    k_agg<<<2048, 256>>>(b3, 0);

    // pool + MLP head
    k_pool<<<NG, 256>>>();
    k_mlp<<<1, 512>>>(Wm0, bnm_g, bnm_b, Wm1, bm1, out);
}

// round 3
// speedup vs baseline: 1.1828x; 1.1828x over previous
#include <cuda_runtime.h>
#include <cuda_bf16.h>

#define NN 400000
#define NE 2500000
#define NG 512
#define HD 32
#define INF 7
#define C2 2
#define EPSF 1e-5f
#define NSCAN ((NN + 1023) / 1024)   // 391

// ---------------- device scratch (static, no runtime alloc) ----------------
__device__ float  g_t[NN * HD];      // transformed features (input to aggregation)
__device__ float  g_agg[NN * HD];    // aggregated output
__device__ float  g_deg[NN];
__device__ float  g_dinv[NN];
__device__ int    g_hist[NN];
__device__ int    g_colptr[NN];
__device__ int    g_cursor[NN];
__device__ int2   g_epair[NE];       // (src, bitcast norm) interleaved
__device__ double g_sum[3][HD];
__device__ double g_sumsq[3][HD];
__device__ int    g_blocksums[512];
__device__ float  g_pool[NG * HD];
__device__ int    g_goff[NG + 1];

// ---------------- preprocessing ----------------
__global__ void k_init() {
    int i = blockIdx.x * blockDim.x + threadIdx.x;
    if (i < NN) { g_deg[i] = 1.0f; g_hist[i] = 0; }   // deg starts at 1 (self-loop w=1)
    if (i < 3 * HD) { ((double*)g_sum)[i] = 0.0; ((double*)g_sumsq)[i] = 0.0; }
}

__global__ void k_edge(const int* __restrict__ ei, const float* __restrict__ ea) {
    int e = blockIdx.x * blockDim.x + threadIdx.x;
    if (e >= NE) return;
    int c = ei[NE + e];
    atomicAdd(&g_deg[c], ea[e]);
    atomicAdd(&g_hist[c], 1);
}

// block-local scan of hist + dinv computation (fused elementwise work)
__global__ void k_scan1() {
    __shared__ int s[1024];
    int t = threadIdx.x;
    int i = blockIdx.x * 1024 + t;
    if (i < NN) {
        float d = g_deg[i];
        g_dinv[i] = (d > 0.0f) ? rsqrtf(fmaxf(d, EPSF)) : 0.0f;
    }
    int v = (i < NN) ? g_hist[i] : 0;
    s[t] = v;
    __syncthreads();
    for (int off = 1; off < 1024; off <<= 1) {
        int x = 0;
        if (t >= off) x = s[t - off];
        __syncthreads();
        s[t] += x;
        __syncthreads();
    }
    if (i < NN) g_colptr[i] = s[t] - v;   // exclusive within block
    if (t == 1023) g_blocksums[blockIdx.x] = s[t];
}

__global__ void k_scan2() {
    __shared__ int s[512];
    int t = threadIdx.x;
    int v = (t < NSCAN) ? g_blocksums[t] : 0;
    s[t] = v;
    __syncthreads();
    for (int off = 1; off < 512; off <<= 1) {
        int x = 0;
        if (t >= off) x = s[t - off];
        __syncthreads();
        s[t] += x;
        __syncthreads();
    }
    if (t < NSCAN) g_blocksums[t] = s[t] - v;   // exclusive block offsets
}

// finalize colptr/cursor + graph offsets (fused)
__global__ void k_scan3(const int* __restrict__ batch) {
    int i = blockIdx.x * blockDim.x + threadIdx.x;
    if (i >= NN) return;
    int v = g_colptr[i] + g_blocksums[i >> 10];
    g_colptr[i] = v;
    g_cursor[i] = v;
    int b = batch[i];
    int prev = (i == 0) ? -1 : batch[i - 1];
    for (int g = prev + 1; g <= b; g++) g_goff[g] = i;
    if (i == NN - 1)
        for (int g = b + 1; g <= NG; g++) g_goff[g] = NN;
}

__global__ void k_scatter(const int* __restrict__ ei, const float* __restrict__ ea) {
    int e = blockIdx.x * blockDim.x + threadIdx.x;
    if (e >= NE) return;
    int r = ei[e];
    int c = ei[NE + e];
    float w = ea[e];
    int pos = atomicAdd(&g_cursor[c], 1);
    float nm = g_dinv[r] * w * g_dinv[c];
    g_epair[pos] = make_int2(r, __float_as_int(nm));
}

// ---------------- layer 0 transform: t = x @ W0 ----------------
__global__ void k_t0(const float* __restrict__ x, const float* __restrict__ W0) {
    __shared__ float sW[INF * HD];
    for (int i = threadIdx.x; i < INF * HD; i += blockDim.x) sW[i] = W0[i];
    __syncthreads();
    int n = blockIdx.x * blockDim.x + threadIdx.x;
    if (n >= NN) return;
    float xi[INF];
#pragma unroll
    for (int k = 0; k < INF; k++) xi[k] = x[n * INF + k];
#pragma unroll
    for (int jq = 0; jq < HD / 4; jq++) {
        float4 a = make_float4(0.f, 0.f, 0.f, 0.f);
#pragma unroll
        for (int k = 0; k < INF; k++) {
            float4 w = *(const float4*)&sW[k * HD + jq * 4];
            a.x += xi[k] * w.x; a.y += xi[k] * w.y;
            a.z += xi[k] * w.z; a.w += xi[k] * w.w;
        }
        *(float4*)&g_t[n * HD + jq * 4] = a;
    }
}

// ---------------- aggregation: warp-per-dest, lane-per-feature, 4x unrolled ----------------
__global__ void k_agg(const float* __restrict__ bias, int layer) {
    __shared__ double ssum[HD], ssq[HD];
    int doStats = (layer >= 0);
    if (doStats) {
        if (threadIdx.x < HD) { ssum[threadIdx.x] = 0.0; ssq[threadIdx.x] = 0.0; }
        __syncthreads();
    }
    int lane = threadIdx.x & 31;
    int gw = (blockIdx.x * blockDim.x + threadIdx.x) >> 5;
    int nw = (gridDim.x * blockDim.x) >> 5;
    double ls = 0.0, lq = 0.0;
    for (int n = gw; n < NN; n += nw) {
        int st = g_colptr[n];
        int cnt = g_hist[n];
        float di = g_dinv[n];
        float acc = di * di * __ldg(&g_t[n * HD + lane]);
        int k = 0;
        for (; k + 4 <= cnt; k += 4) {
            int2 p0 = __ldg(&g_epair[st + k + 0]);
            int2 p1 = __ldg(&g_epair[st + k + 1]);
            int2 p2 = __ldg(&g_epair[st + k + 2]);
            int2 p3 = __ldg(&g_epair[st + k + 3]);
            float v0 = __ldg(&g_t[p0.x * HD + lane]);
            float v1 = __ldg(&g_t[p1.x * HD + lane]);
            float v2 = __ldg(&g_t[p2.x * HD + lane]);
            float v3 = __ldg(&g_t[p3.x * HD + lane]);
            acc += __int_as_float(p0.y) * v0;
            acc += __int_as_float(p1.y) * v1;
            acc += __int_as_float(p2.y) * v2;
            acc += __int_as_float(p3.y) * v3;
        }
        for (; k < cnt; k++) {
            int2 p = __ldg(&g_epair[st + k]);
            acc += __int_as_float(p.y) * __ldg(&g_t[p.x * HD + lane]);
        }
        if (bias) acc += bias[lane];
        g_agg[n * HD + lane] = acc;
        if (doStats) { ls += acc; lq += (double)acc * (double)acc; }
    }
    if (doStats) {
        atomicAdd(&ssum[lane], ls);
        atomicAdd(&ssq[lane], lq);
        __syncthreads();
        if (threadIdx.x < HD) {
            atomicAdd(&g_sum[layer][threadIdx.x], ssum[threadIdx.x]);
            atomicAdd(&g_sumsq[layer][threadIdx.x], ssq[threadIdx.x]);
        }
    }
}

// ---------------- fused bn-finalize + bn + relu + transform ----------------
__global__ void k_bnt(const float* __restrict__ W, const float* __restrict__ gvec,
                      const float* __restrict__ bvec, int layer) {
    __shared__ float sW[HD * HD];
    __shared__ float ssc[HD], ssh[HD];
    for (int i = threadIdx.x; i < HD * HD; i += blockDim.x) sW[i] = W[i];
    if (threadIdx.x < HD) {
        int j = threadIdx.x;
        double mean = g_sum[layer][j] / (double)NN;
        double var = g_sumsq[layer][j] / (double)NN - mean * mean;
        float rstd = (float)rsqrt(var + (double)EPSF);
        float sc = gvec[j] * rstd;
        ssc[j] = sc;
        ssh[j] = bvec[j] - (float)mean * sc;
    }
    __syncthreads();
    int n = blockIdx.x * blockDim.x + threadIdx.x;
    if (n >= NN) return;
    float y[HD];
#pragma unroll
    for (int kq = 0; kq < HD / 4; kq++) {
        float4 a = *(const float4*)&g_agg[n * HD + kq * 4];
        y[kq * 4 + 0] = fmaxf(a.x * ssc[kq * 4 + 0] + ssh[kq * 4 + 0], 0.f);
        y[kq * 4 + 1] = fmaxf(a.y * ssc[kq * 4 + 1] + ssh[kq * 4 + 1], 0.f);
        y[kq * 4 + 2] = fmaxf(a.z * ssc[kq * 4 + 2] + ssh[kq * 4 + 2], 0.f);
        y[kq * 4 + 3] = fmaxf(a.w * ssc[kq * 4 + 3] + ssh[kq * 4 + 3], 0.f);
    }
#pragma unroll
    for (int jq = 0; jq < HD / 4; jq++) {
        float4 a = make_float4(0.f, 0.f, 0.f, 0.f);
#pragma unroll
        for (int k = 0; k < HD; k++) {
            float4 w = *(const float4*)&sW[k * HD + jq * 4];
            a.x += y[k] * w.x; a.y += y[k] * w.y;
            a.z += y[k] * w.z; a.w += y[k] * w.w;
        }
        *(float4*)&g_t[n * HD + jq * 4] = a;
    }
}

// ---------------- pool: block per graph (batch is sorted) ----------------
__global__ void k_pool() {
    int g = blockIdx.x;
    int s = g_goff[g], e = g_goff[g + 1];
    int j = threadIdx.x & 31, r = threadIdx.x >> 5;
    float a = 0.f;
    for (int n = s + r; n < e; n += 8) a += g_agg[n * HD + j];
    __shared__ float sm[256];
    sm[threadIdx.x] = a;
    __syncthreads();
    if (threadIdx.x < 32) {
        float p = 0.f;
#pragma unroll
        for (int q = 0; q < 8; q++) p += sm[q * 32 + threadIdx.x];
        g_pool[g * HD + threadIdx.x] = p;
    }
}

// ---------------- final MLP, single block, 512 threads (one per graph) ----------------
__global__ void k_mlp(const float* __restrict__ Wm0, const float* __restrict__ gm,
                      const float* __restrict__ bm, const float* __restrict__ Wm1,
                      const float* __restrict__ bm1, float* __restrict__ out) {
    __shared__ float sW0[HD * HD];
    __shared__ float sW1[HD * C2];
    __shared__ double ssum[HD], ssq[HD];
    __shared__ float ssc[HD], ssh[HD];
    int t = threadIdx.x;
    for (int i = t; i < HD * HD; i += blockDim.x) sW0[i] = Wm0[i];
    if (t < HD * C2) sW1[t] = Wm1[t];
    if (t < HD) { ssum[t] = 0.0; ssq[t] = 0.0; }
    __syncthreads();

    float p[HD];
#pragma unroll
    for (int k = 0; k < HD; k++) p[k] = g_pool[t * HD + k];
    float u[HD];
#pragma unroll
    for (int j = 0; j < HD; j++) {
        float a = 0.f;
#pragma unroll
        for (int k = 0; k < HD; k++) a += p[k] * sW0[k * HD + j];
        u[j] = a;
    }
    int lane = t & 31;
#pragma unroll
    for (int j = 0; j < HD; j++) {
        float v = u[j];
        float q = u[j] * u[j];
        for (int off = 16; off > 0; off >>= 1) {
            v += __shfl_down_sync(0xFFFFFFFFu, v, off);
            q += __shfl_down_sync(0xFFFFFFFFu, q, off);
        }
        if (lane == 0) {
            atomicAdd(&ssum[j], (double)v);
            atomicAdd(&ssq[j], (double)q);
        }
    }
    __syncthreads();
    if (t < HD) {
        double mean = ssum[t] / (double)NG;
        double var = ssq[t] / (double)NG - mean * mean;
        float rstd = (float)rsqrt(var + (double)EPSF);
        ssc[t] = gm[t] * rstd;
        ssh[t] = bm[t] - (float)mean * gm[t] * rstd;
    }
    __syncthreads();
    float o0 = bm1[0], o1 = bm1[1];
#pragma unroll
    for (int k = 0; k < HD; k++) {
        float yv = fmaxf(u[k] * ssc[k] + ssh[k], 0.f);
        o0 += yv * sW1[k * 2 + 0];
        o1 += yv * sW1[k * 2 + 1];
    }
    out[t * 2 + 0] = o0;
    out[t * 2 + 1] = o1;
}

// ---------------- launch ----------------
extern "C" void kernel_launch(void* const* d_in, const int* in_sizes, int n_in,
                              void* d_out, int out_size) {
    const float* x     = (const float*)d_in[0];
    const int*   ei    = (const int*)d_in[1];     // int32 (JAX x64 disabled)
    const float* ea    = (const float*)d_in[2];
    const int*   batch = (const int*)d_in[3];     // int32
    const float* W0    = (const float*)d_in[4];
    const float* W1    = (const float*)d_in[6];   // b0..b2, bm0 cancel in batchnorm
    const float* W2    = (const float*)d_in[8];
    const float* W3    = (const float*)d_in[10];
    const float* b3    = (const float*)d_in[11];
    const float* bn_g  = (const float*)d_in[12];  // [3,32]
    const float* bn_b  = (const float*)d_in[13];
    const float* Wm0   = (const float*)d_in[14];
    const float* bnm_g = (const float*)d_in[16];
    const float* bnm_b = (const float*)d_in[17];
    const float* Wm1   = (const float*)d_in[18];
    const float* bm1   = (const float*)d_in[19];
    float* out = (float*)d_out;

    const int nb = (NN + 255) / 256;
    const int eb = (NE + 255) / 256;

    // per-replay preprocessing: degrees, CSC, graph offsets
    k_init<<<nb, 256>>>();
    k_edge<<<eb, 256>>>(ei, ea);
    k_scan1<<<NSCAN, 1024>>>();
    k_scan2<<<1, 512>>>();
    k_scan3<<<nb, 256>>>(batch);
    k_scatter<<<eb, 256>>>(ei, ea);

    // layer 0
    k_t0<<<nb, 256>>>(x, W0);
    k_agg<<<2048, 256>>>(nullptr, 0);
    k_bnt<<<nb, 256>>>(W1, bn_g + 0 * HD, bn_b + 0 * HD, 0);
    // layer 1
    k_agg<<<2048, 256>>>(nullptr, 1);
    k_bnt<<<nb, 256>>>(W2, bn_g + 1 * HD, bn_b + 1 * HD, 1);
    // layer 2
    k_agg<<<2048, 256>>>(nullptr, 2);
    k_bnt<<<nb, 256>>>(W3, bn_g + 2 * HD, bn_b + 2 * HD, 2);
    // layer 3 (bias, no bn)
    k_agg<<<2048, 256>>>(b3, -1);

    // pool + MLP head
    k_pool<<<NG, 256>>>();
    k_mlp<<<1, 512>>>(Wm0, bnm_g, bnm_b, Wm1, bm1, out);
}

// round 4
// speedup vs baseline: 1.3370x; 1.1303x over previous
#include <cuda_runtime.h>
#include <cuda_bf16.h>

#define NN 400000
#define NE 2500000
#define NG 512
#define HD 32
#define INF 7
#define C2 2
#define EPSF 1e-5f
#define NSCAN ((NN + 1023) / 1024)   // 391
#define CHUNK 25
#define AGG_BLOCKS 2000              // 2000*8 warps * 25 nodes = 400000 exactly

// ---------------- device scratch (static, no runtime alloc) ----------------
__device__ float  g_t[NN * HD];      // t' = dinv[n] * (features @ W)
__device__ float  g_agg[NN * HD];
__device__ float  g_dinv[NN];
__device__ int    g_hist[NN];
__device__ int    g_colptr[NN];
__device__ int    g_cursor[NN];
__device__ int2   g_epair[NE];       // (src, bitcast w) interleaved
__device__ double g_sum[3][HD];
__device__ double g_sumsq[3][HD];
__device__ int    g_blocksums[512];
__device__ float  g_pool[NG * HD];
__device__ int    g_goff[NG + 1];

// ---------------- preprocessing ----------------
__global__ void k_init() {
    int i = blockIdx.x * blockDim.x + threadIdx.x;
    if (i < NN) g_hist[i] = 0;
    if (i < 3 * HD) { ((double*)g_sum)[i] = 0.0; ((double*)g_sumsq)[i] = 0.0; }
}

__global__ void k_edge(const int* __restrict__ ei) {
    int e = blockIdx.x * blockDim.x + threadIdx.x;
    if (e >= NE) return;
    atomicAdd(&g_hist[ei[NE + e]], 1);
}

__global__ void k_scan1() {
    __shared__ int s[1024];
    int t = threadIdx.x;
    int i = blockIdx.x * 1024 + t;
    int v = (i < NN) ? g_hist[i] : 0;
    s[t] = v;
    __syncthreads();
    for (int off = 1; off < 1024; off <<= 1) {
        int x = 0;
        if (t >= off) x = s[t - off];
        __syncthreads();
        s[t] += x;
        __syncthreads();
    }
    if (i < NN) g_colptr[i] = s[t] - v;   // exclusive within block
    if (t == 1023) g_blocksums[blockIdx.x] = s[t];
}

__global__ void k_scan2() {
    __shared__ int s[512];
    int t = threadIdx.x;
    int v = (t < NSCAN) ? g_blocksums[t] : 0;
    s[t] = v;
    __syncthreads();
    for (int off = 1; off < 512; off <<= 1) {
        int x = 0;
        if (t >= off) x = s[t - off];
        __syncthreads();
        s[t] += x;
        __syncthreads();
    }
    if (t < NSCAN) g_blocksums[t] = s[t] - v;
}

// finalize colptr/cursor + graph offsets (fused)
__global__ void k_scan3(const int* __restrict__ batch) {
    int i = blockIdx.x * blockDim.x + threadIdx.x;
    if (i >= NN) return;
    int v = g_colptr[i] + g_blocksums[i >> 10];
    g_colptr[i] = v;
    g_cursor[i] = v;
    int b = batch[i];
    int prev = (i == 0) ? -1 : batch[i - 1];
    for (int g = prev + 1; g <= b; g++) g_goff[g] = i;
    if (i == NN - 1)
        for (int g = b + 1; g <= NG; g++) g_goff[g] = NN;
}

// scatter raw (src, w) — no dinv dependence
__global__ void k_scatter(const int* __restrict__ ei, const float* __restrict__ ea) {
    int e = blockIdx.x * blockDim.x + threadIdx.x;
    if (e >= NE) return;
    int r = ei[e];
    int c = ei[NE + e];
    int pos = atomicAdd(&g_cursor[c], 1);
    g_epair[pos] = make_int2(r, __float_as_int(ea[e]));
}

// ---------------- fused deg/dinv + layer-0 transform: t' = dinv * (x @ W0) ----------------
__global__ void k_t0deg(const float* __restrict__ x, const float* __restrict__ W0) {
    __shared__ float sW[INF * HD];
    for (int i = threadIdx.x; i < INF * HD; i += blockDim.x) sW[i] = W0[i];
    __syncthreads();
    int n = blockIdx.x * blockDim.x + threadIdx.x;
    if (n >= NN) return;
    // weighted degree from contiguous CSC segment (self-loop weight 1)
    int st = g_colptr[n];
    int en = (n + 1 < NN) ? __ldg(&g_colptr[n + 1]) : NE;
    float deg = 1.0f;
    for (int k = st; k < en; k++) deg += __int_as_float(__ldg(&g_epair[k].y));
    float dn = rsqrtf(fmaxf(deg, EPSF));   // deg >= 1 always (self loop)
    g_dinv[n] = dn;

    float xi[INF];
#pragma unroll
    for (int k = 0; k < INF; k++) xi[k] = x[n * INF + k];
#pragma unroll
    for (int jq = 0; jq < HD / 4; jq++) {
        float4 a = make_float4(0.f, 0.f, 0.f, 0.f);
#pragma unroll
        for (int k = 0; k < INF; k++) {
            float4 w = *(const float4*)&sW[k * HD + jq * 4];
            a.x += xi[k] * w.x; a.y += xi[k] * w.y;
            a.z += xi[k] * w.z; a.w += xi[k] * w.w;
        }
        a.x *= dn; a.y *= dn; a.z *= dn; a.w *= dn;
        *(float4*)&g_t[n * HD + jq * 4] = a;
    }
}

// ---------------- aggregation: contiguous node chunk per warp, lane-per-feature ----------------
__global__ void k_agg(const float* __restrict__ bias, int layer) {
    __shared__ double ssum[HD], ssq[HD];
    int doStats = (layer >= 0);
    if (doStats) {
        if (threadIdx.x < HD) { ssum[threadIdx.x] = 0.0; ssq[threadIdx.x] = 0.0; }
        __syncthreads();
    }
    int lane = threadIdx.x & 31;
    int gw = (blockIdx.x * blockDim.x + threadIdx.x) >> 5;
    int n0 = gw * CHUNK;
    double ls = 0.0, lq = 0.0;
    float bl = bias ? bias[lane] : 0.0f;
    if (n0 < NN) {
        int n1 = min(n0 + CHUNK, NN);
        int st = __ldg(&g_colptr[n0]);
        for (int n = n0; n < n1; n++) {
            int en = (n + 1 < NN) ? __ldg(&g_colptr[n + 1]) : NE;
            float dc = __ldg(&g_dinv[n]);
            float acc = __ldg(&g_t[n * HD + lane]);          // t'[c]
            int k = st;
            for (; k + 4 <= en; k += 4) {
                int2 p0 = __ldg(&g_epair[k + 0]);
                int2 p1 = __ldg(&g_epair[k + 1]);
                int2 p2 = __ldg(&g_epair[k + 2]);
                int2 p3 = __ldg(&g_epair[k + 3]);
                float v0 = __ldg(&g_t[p0.x * HD + lane]);
                float v1 = __ldg(&g_t[p1.x * HD + lane]);
                float v2 = __ldg(&g_t[p2.x * HD + lane]);
                float v3 = __ldg(&g_t[p3.x * HD + lane]);
                acc += __int_as_float(p0.y) * v0;
                acc += __int_as_float(p1.y) * v1;
                acc += __int_as_float(p2.y) * v2;
                acc += __int_as_float(p3.y) * v3;
            }
            for (; k < en; k++) {
                int2 p = __ldg(&g_epair[k]);
                acc += __int_as_float(p.y) * __ldg(&g_t[p.x * HD + lane]);
            }
            acc = dc * acc + bl;
            g_agg[n * HD + lane] = acc;
            if (doStats) { ls += acc; lq += (double)acc * (double)acc; }
            st = en;
        }
    }
    if (doStats) {
        atomicAdd(&ssum[lane], ls);
        atomicAdd(&ssq[lane], lq);
        __syncthreads();
        if (threadIdx.x < HD) {
            atomicAdd(&g_sum[layer][threadIdx.x], ssum[threadIdx.x]);
            atomicAdd(&g_sumsq[layer][threadIdx.x], ssq[threadIdx.x]);
        }
    }
}

// ---------------- fused bn-finalize + bn + relu + transform (+ dinv scale) ----------------
__global__ void k_bnt(const float* __restrict__ W, const float* __restrict__ gvec,
                      const float* __restrict__ bvec, int layer) {
    __shared__ float sW[HD * HD];
    __shared__ float ssc[HD], ssh[HD];
    for (int i = threadIdx.x; i < HD * HD; i += blockDim.x) sW[i] = W[i];
    if (threadIdx.x < HD) {
        int j = threadIdx.x;
        double mean = g_sum[layer][j] / (double)NN;
        double var = g_sumsq[layer][j] / (double)NN - mean * mean;
        float rstd = (float)rsqrt(var + (double)EPSF);
        float sc = gvec[j] * rstd;
        ssc[j] = sc;
        ssh[j] = bvec[j] - (float)mean * sc;
    }
    __syncthreads();
    int n = blockIdx.x * blockDim.x + threadIdx.x;
    if (n >= NN) return;
    float dn = __ldg(&g_dinv[n]);
    float y[HD];
#pragma unroll
    for (int kq = 0; kq < HD / 4; kq++) {
        float4 a = *(const float4*)&g_agg[n * HD + kq * 4];
        y[kq * 4 + 0] = fmaxf(a.x * ssc[kq * 4 + 0] + ssh[kq * 4 + 0], 0.f);
        y[kq * 4 + 1] = fmaxf(a.y * ssc[kq * 4 + 1] + ssh[kq * 4 + 1], 0.f);
        y[kq * 4 + 2] = fmaxf(a.z * ssc[kq * 4 + 2] + ssh[kq * 4 + 2], 0.f);
        y[kq * 4 + 3] = fmaxf(a.w * ssc[kq * 4 + 3] + ssh[kq * 4 + 3], 0.f);
    }
#pragma unroll
    for (int jq = 0; jq < HD / 4; jq++) {
        float4 a = make_float4(0.f, 0.f, 0.f, 0.f);
#pragma unroll
        for (int k = 0; k < HD; k++) {
            float4 w = *(const float4*)&sW[k * HD + jq * 4];
            a.x += y[k] * w.x; a.y += y[k] * w.y;
            a.z += y[k] * w.z; a.w += y[k] * w.w;
        }
        a.x *= dn; a.y *= dn; a.z *= dn; a.w *= dn;
        *(float4*)&g_t[n * HD + jq * 4] = a;
    }
}

// ---------------- pool: block per graph (batch is sorted) ----------------
__global__ void k_pool() {
    int g = blockIdx.x;
    int s = g_goff[g], e = g_goff[g + 1];
    int j = threadIdx.x & 31, r = threadIdx.x >> 5;
    float a = 0.f;
    for (int n = s + r; n < e; n += 8) a += g_agg[n * HD + j];
    __shared__ float sm[256];
    sm[threadIdx.x] = a;
    __syncthreads();
    if (threadIdx.x < 32) {
        float p = 0.f;
#pragma unroll
        for (int q = 0; q < 8; q++) p += sm[q * 32 + threadIdx.x];
        g_pool[g * HD + threadIdx.x] = p;
    }
}

// ---------------- final MLP, single block, 512 threads (one per graph) ----------------
__global__ void k_mlp(const float* __restrict__ Wm0, const float* __restrict__ gm,
                      const float* __restrict__ bm, const float* __restrict__ Wm1,
                      const float* __restrict__ bm1, float* __restrict__ out) {
    __shared__ float sW0[HD * HD];
    __shared__ float sW1[HD * C2];
    __shared__ double ssum[HD], ssq[HD];
    __shared__ float ssc[HD], ssh[HD];
    int t = threadIdx.x;
    for (int i = t; i < HD * HD; i += blockDim.x) sW0[i] = Wm0[i];
    if (t < HD * C2) sW1[t] = Wm1[t];
    if (t < HD) { ssum[t] = 0.0; ssq[t] = 0.0; }
    __syncthreads();

    float p[HD];
#pragma unroll
    for (int k = 0; k < HD; k++) p[k] = g_pool[t * HD + k];
    float u[HD];
#pragma unroll
    for (int j = 0; j < HD; j++) {
        float a = 0.f;
#pragma unroll
        for (int k = 0; k < HD; k++) a += p[k] * sW0[k * HD + j];
        u[j] = a;
    }
    int lane = t & 31;
#pragma unroll
    for (int j = 0; j < HD; j++) {
        float v = u[j];
        float q = u[j] * u[j];
        for (int off = 16; off > 0; off >>= 1) {
            v += __shfl_down_sync(0xFFFFFFFFu, v, off);
            q += __shfl_down_sync(0xFFFFFFFFu, q, off);
        }
        if (lane == 0) {
            atomicAdd(&ssum[j], (double)v);
            atomicAdd(&ssq[j], (double)q);
        }
    }
    __syncthreads();
    if (t < HD) {
        double mean = ssum[t] / (double)NG;
        double var = ssq[t] / (double)NG - mean * mean;
        float rstd = (float)rsqrt(var + (double)EPSF);
        ssc[t] = gm[t] * rstd;
        ssh[t] = bm[t] - (float)mean * gm[t] * rstd;
    }
    __syncthreads();
    float o0 = bm1[0], o1 = bm1[1];
#pragma unroll
    for (int k = 0; k < HD; k++) {
        float yv = fmaxf(u[k] * ssc[k] + ssh[k], 0.f);
        o0 += yv * sW1[k * 2 + 0];
        o1 += yv * sW1[k * 2 + 1];
    }
    out[t * 2 + 0] = o0;
    out[t * 2 + 1] = o1;
}

// ---------------- launch ----------------
extern "C" void kernel_launch(void* const* d_in, const int* in_sizes, int n_in,
                              void* d_out, int out_size) {
    const float* x     = (const float*)d_in[0];
    const int*   ei    = (const int*)d_in[1];     // int32 (JAX x64 disabled)
    const float* ea    = (const float*)d_in[2];
    const int*   batch = (const int*)d_in[3];     // int32
    const float* W0    = (const float*)d_in[4];
    const float* W1    = (const float*)d_in[6];   // b0..b2, bm0 cancel in batchnorm
    const float* W2    = (const float*)d_in[8];
    const float* W3    = (const float*)d_in[10];
    const float* b3    = (const float*)d_in[11];
    const float* bn_g  = (const float*)d_in[12];  // [3,32]
    const float* bn_b  = (const float*)d_in[13];
    const float* Wm0   = (const float*)d_in[14];
    const float* bnm_g = (const float*)d_in[16];
    const float* bnm_b = (const float*)d_in[17];
    const float* Wm1   = (const float*)d_in[18];
    const float* bm1   = (const float*)d_in[19];
    float* out = (float*)d_out;

    const int nb = (NN + 255) / 256;
    const int eb = (NE + 255) / 256;

    // per-replay preprocessing: histogram, CSC, graph offsets
    k_init<<<nb, 256>>>();
    k_edge<<<eb, 256>>>(ei);
    k_scan1<<<NSCAN, 1024>>>();
    k_scan2<<<1, 512>>>();
    k_scan3<<<nb, 256>>>(batch);
    k_scatter<<<eb, 256>>>(ei, ea);

    // layer 0 (fused deg/dinv + transform)
    k_t0deg<<<nb, 256>>>(x, W0);
    k_agg<<<AGG_BLOCKS, 256>>>(nullptr, 0);
    k_bnt<<<nb, 256>>>(W1, bn_g + 0 * HD, bn_b + 0 * HD, 0);
    // layer 1
    k_agg<<<AGG_BLOCKS, 256>>>(nullptr, 1);
    k_bnt<<<nb, 256>>>(W2, bn_g + 1 * HD, bn_b + 1 * HD, 1);
    // layer 2
    k_agg<<<AGG_BLOCKS, 256>>>(nullptr, 2);
    k_bnt<<<nb, 256>>>(W3, bn_g + 2 * HD, bn_b + 2 * HD, 2);
    // layer 3 (bias, no bn)
    k_agg<<<AGG_BLOCKS, 256>>>(b3, -1);

    // pool + MLP head
    k_pool<<<NG, 256>>>();
    k_mlp<<<1, 512>>>(Wm0, bnm_g, bnm_b, Wm1, bm1, out);
}